// round 9
// baseline (speedup 1.0000x reference)
#include <cuda_runtime.h>
#include <cstdint>
#include <cstddef>

#define S    512
#define TT   2048
#define NB   16
#define CLU  8
#define CPC  64          // columns per CTA
#define NTHR 512         // 16 warps, 4 cols per warp
#define NW   16
#define LN_EPS 1e-5f

typedef unsigned long long ull;

// One 272B message per (src CTA, step): 64 z floats + (s1,s2) + pad to 16B
#define MSG_FLTS 68
#define MSG_BYTES 272
#define STEP_TX_BYTES (8u * MSG_BYTES)   // 2176

// ---------------- scratch (allocation-free rule: __device__ globals) ----------
__device__ float g_bufU[(size_t)NB * TT * S];   // 64MB
__device__ float g_bufH[(size_t)NB * TT * S];   // 64MB
__device__ float g_W01[(size_t)S * S];          // 1MB
__device__ float g_dummy[32];

// ---------------- PTX helpers -------------------------------------------------
__device__ __forceinline__ uint32_t smem_u32(const void* p) {
    return (uint32_t)__cvta_generic_to_shared(p);
}
__device__ __forceinline__ uint32_t mapa_shared(uint32_t addr, int rank) {
    uint32_t out;
    asm("mapa.shared::cluster.u32 %0, %1, %2;" : "=r"(out) : "r"(addr), "r"(rank));
    return out;
}
__device__ __forceinline__ void bulk_cluster(uint32_t dst, uint32_t src,
                                             uint32_t bytes, uint32_t mbar) {
    asm volatile(
        "cp.async.bulk.shared::cluster.shared::cta.mbarrier::complete_tx::bytes "
        "[%0], [%1], %2, [%3];"
        :: "r"(dst), "r"(src), "r"(bytes), "r"(mbar) : "memory");
}
__device__ __forceinline__ void fence_proxy_async_cta() {
    asm volatile("fence.proxy.async.shared::cta;" ::: "memory");
}
__device__ __forceinline__ void mbar_init(uint32_t addr, uint32_t cnt) {
    asm volatile("mbarrier.init.shared.b64 [%0], %1;" :: "r"(addr), "r"(cnt) : "memory");
}
__device__ __forceinline__ void mbar_expect_tx(uint32_t addr, uint32_t bytes) {
    asm volatile("mbarrier.arrive.expect_tx.shared.b64 _, [%0], %1;"
                 :: "r"(addr), "r"(bytes) : "memory");
}
__device__ __forceinline__ void mbar_wait_parity(uint32_t addr, uint32_t phase) {
    uint32_t done = 0;
    while (!done) {
        asm volatile(
            "{\n\t.reg .pred p;\n\t"
            "mbarrier.try_wait.parity.acquire.cta.shared::cta.b64 p, [%1], %2, 0x989680;\n\t"
            "selp.b32 %0, 1, 0, p;\n\t}"
            : "=r"(done) : "r"(addr), "r"(phase) : "memory");
    }
}
__device__ __forceinline__ void cluster_barrier() {
    asm volatile("barrier.cluster.arrive.aligned;" ::: "memory");
    asm volatile("barrier.cluster.wait.aligned;"  ::: "memory");
}
__device__ __forceinline__ ull pk(float x, float y) {
    ull r; asm("mov.b64 %0, {%1, %2};" : "=l"(r) : "f"(x), "f"(y)); return r;
}
__device__ __forceinline__ float2 upk(ull v) {
    float2 r; asm("mov.b64 {%0, %1}, %2;" : "=f"(r.x), "=f"(r.y) : "l"(v)); return r;
}
__device__ __forceinline__ ull ffma2(ull a, ull b, ull c) {
    ull d; asm("fma.rn.f32x2 %0, %1, %2, %3;" : "=l"(d) : "l"(a), "l"(b), "l"(c)); return d;
}

// ---------------- scan kernel -------------------------------------------------
// grid = 128 CTAs = 16 clusters of 8. Cluster c = batch c. 512 threads:
// 16 warps x 4 cols. kp[4][4][2] = 64 regs (no spills). Per step: FFMA2
// matmul -> butterfly -> stage 64 z + per-warp partials -> sync -> warp0
// reduces 16 partial pairs to 1 and sends ONE 272B bulk per rank -> wait ->
// 3-round partial reduce over 8 sources -> 1 col/thread LN+GELU -> h_sm.
extern __shared__ float sm[];

// sm[0..4): 2 mbarriers (16B)
#define A_OFF   16
#define H_OFF   (A_OFF + CPC * S)             // h [512]
#define CB_OFF  (H_OFF + S)                   // comb [2][8][68]
#define ST_OFF  (CB_OFF + 2 * 8 * MSG_FLTS)   // stage [2][68]
#define PT_OFF  (ST_OFF + 2 * MSG_FLTS)       // part [2][32]
#define SM_FLTS (PT_OFF + 2 * 32)
static const size_t SCAN_SMEM = (size_t)SM_FLTS * sizeof(float);

__global__ void __cluster_dims__(CLU, 1, 1) __launch_bounds__(NTHR, 1)
scan_kernel(const float* __restrict__ Aw, const float* __restrict__ Kw,
            const float* __restrict__ ab, const float* __restrict__ gg,
            const float* __restrict__ bb, const float* __restrict__ U,
            float* __restrict__ HS)
{
    float* A_sm  = sm + A_OFF;             // [64][512]
    float* h_sm  = sm + H_OFF;             // [512]
    float* comb  = sm + CB_OFF;            // [2][8][68]
    float* stage = sm + ST_OFF;            // [2][68]
    float* part  = sm + PT_OFF;            // [2][16][2]

    const uint32_t mbar_u = smem_u32(sm);  // mbar[m] at +8m
    const int tid  = threadIdx.x;
    const int lane = tid & 31;
    const int w    = tid >> 5;             // warp 0..15
    const int batch = blockIdx.x / CLU;
    const int rank  = blockIdx.x % CLU;
    const int colbase = rank * CPC;
    const int wcol = colbase + 4 * w;      // first global col of this warp

    if (tid < 2) {
        mbar_init(mbar_u + tid * 8, 1);
        mbar_expect_tx(mbar_u + tid * 8, STEP_TX_BYTES);
    }

    // A slice: A_sm[c][j] = Aw[j*S + colbase + c]
    for (int idx = tid; idx < CPC * S; idx += NTHR) {
        int j = idx >> 6, c = idx & 63;
        A_sm[c * S + j] = Aw[(size_t)j * S + colbase + c];
    }
    for (int i = tid; i < S; i += NTHR) h_sm[i] = 0.f;

    // K packed: kp[c][r][p] = (K[k0+2p][wcol+c], K[k0+2p+1][wcol+c]), k0=4*lane+128*r
    ull kp[4][4][2];
#pragma unroll
    for (int c = 0; c < 4; c++)
#pragma unroll
        for (int r = 0; r < 4; r++) {
            int k0 = 4 * lane + 128 * r;
            kp[c][r][0] = pk(Kw[(size_t)(k0 + 0) * S + wcol + c],
                             Kw[(size_t)(k0 + 1) * S + wcol + c]);
            kp[c][r][1] = pk(Kw[(size_t)(k0 + 2) * S + wcol + c],
                             Kw[(size_t)(k0 + 3) * S + wcol + c]);
        }
    float abv[4];
#pragma unroll
    for (int c = 0; c < 4; c++) abv[c] = ab[wcol + c];

    const float gv = gg[tid];
    const float bv = bb[tid];
    float hreg = 0.f;

    // bulk-issue addresses (warp0 lanes 0-7; lane L -> rank L)
    const uint32_t cb_dst = mapa_shared(smem_u32(comb), lane & 7);
    const uint32_t mb_dst = mapa_shared(mbar_u, lane & 7);
    const uint32_t st_src = smem_u32(stage);

    __syncthreads();
    cluster_barrier();   // mbarrier init + arming visible before any bulk

    const float* Ub = U  + (size_t)batch * TT * S;
    float*       Hb = HS + (size_t)batch * TT * S;

    for (int t = 0; t < TT; t++) {
        const int m   = t & 1;
        const int par = (t >> 1) & 1;

        // u(t); u(t-1) reload (L1 hit: same line read as uc last step)
        float uc[4], up[4];
        *(float4*)&uc[0] = *(const float4*)&Ub[(size_t)t * S + wcol];
        if (t > 0) {
            *(float4*)&up[0] = *(const float4*)&Ub[(size_t)(t - 1) * S + wcol];
        } else {
#pragma unroll
            for (int c = 0; c < 4; c++) up[c] = 0.f;
        }

        // h pairs (ulonglong2 = LDS.128)
        ull hp[4][2];
#pragma unroll
        for (int r = 0; r < 4; r++) {
            ulonglong2 hv = *(const ulonglong2*)&h_sm[4 * lane + 128 * r];
            hp[r][0] = hv.x; hp[r][1] = hv.y;
        }

        ull accA[4], accK[4];
#pragma unroll
        for (int c = 0; c < 4; c++) { accA[c] = 0ull; accK[c] = 0ull; }
#pragma unroll
        for (int c = 0; c < 4; c++) {
            const float* Ac = A_sm + (size_t)(4 * w + c) * S;
#pragma unroll
            for (int r = 0; r < 4; r++) {
                ulonglong2 av = *(const ulonglong2*)&Ac[4 * lane + 128 * r];
                accA[c] = ffma2(av.x, hp[r][0], accA[c]);
                accA[c] = ffma2(av.y, hp[r][1], accA[c]);
                accK[c] = ffma2(kp[c][r][0], hp[r][0], accK[c]);
                accK[c] = ffma2(kp[c][r][1], hp[r][1], accK[c]);
            }
        }
        float z[4];
#pragma unroll
        for (int c = 0; c < 4; c++) {
            float2 a = upk(accA[c]), k = upk(accK[c]);
            z[c] = (a.x + a.y) + (k.x + k.y) * up[c];
        }
#pragma unroll
        for (int off = 16; off > 0; off >>= 1) {
#pragma unroll
            for (int c = 0; c < 4; c++)
                z[c] += __shfl_xor_sync(0xffffffffu, z[c], off);
        }
        float s1 = 0.f, s2 = 0.f;
#pragma unroll
        for (int c = 0; c < 4; c++) {
            z[c] += abv[c] + uc[c];
            s1 += z[c];
            s2 += z[c] * z[c];
        }

        // ---- stage: 4 z per warp, per-warp (s1,s2)
        if (lane < 4) stage[m * MSG_FLTS + 4 * w + lane] = z[lane];
        if (lane == 0) *(float2*)&part[m * 32 + 2 * w] = make_float2(s1, s2);
        __syncthreads();                    // all warps staged

        // ---- warp 0: reduce 16 partial pairs -> 1, then one bulk per rank
        if (w == 0) {
            float2 pp = *(const float2*)&part[m * 32 + 2 * (lane & 15)];
            float r1 = pp.x, r2 = pp.y;
#pragma unroll
            for (int off = 8; off > 0; off >>= 1) {
                r1 += __shfl_xor_sync(0xffffffffu, r1, off);
                r2 += __shfl_xor_sync(0xffffffffu, r2, off);
            }
            if (lane == 0)
                *(float2*)&stage[m * MSG_FLTS + 64] = make_float2(r1, r2);
            __syncwarp();
            if (lane < 8) {
                fence_proxy_async_cta();
                bulk_cluster(cb_dst + (uint32_t)((m * 8 + rank) * MSG_BYTES),
                             st_src + (uint32_t)(m * MSG_BYTES),
                             MSG_BYTES,
                             mb_dst + (uint32_t)(m * 8));
            }
        }

        // ---- consume
        mbar_wait_parity(mbar_u + m * 8, (uint32_t)par);
        if (tid == 0) mbar_expect_tx(mbar_u + m * 8, STEP_TX_BYTES);  // re-arm t+2

        // 8 source partial pairs -> full LN sums (3 butterfly rounds)
        const float* cb = comb + m * 8 * MSG_FLTS;
        float2 pq = *(const float2*)&cb[(lane & 7) * MSG_FLTS + 64];
        float t1 = pq.x, t2 = pq.y;
#pragma unroll
        for (int off = 4; off > 0; off >>= 1) {
            t1 += __shfl_xor_sync(0xffffffffu, t1, off);
            t2 += __shfl_xor_sync(0xffffffffu, t2, off);
        }
        const float mu   = t1 * (1.f / S);
        const float rinv = rsqrtf(t2 * (1.f / S) - mu * mu + LN_EPS);

        // one column per thread
        float zv = cb[(tid >> 6) * MSG_FLTS + (tid & 63)];
        float zn = (zv - mu) * rinv * gv + bv;
        hreg += 0.5f * zn * (1.f + erff(zn * 0.70710678118654752f));
        h_sm[tid] = hreg;
        if (rank == 0) Hb[(size_t)t * S + tid] = hreg;
        __syncthreads();   // h_sm complete before next step's matmul
    }
    cluster_barrier();     // no CTA exits while peers may still touch its smem
}

// ---------------- dummy (shifts ncu -s 5 onto the 2nd scan) -------------------
__global__ void dummy_kernel() {
    if (threadIdx.x < 32) g_dummy[threadIdx.x] = 0.f;
}

// ---------------- fp32 tiled GEMM:  C[M,N] = A[M,K] * B[K,N]  (all row-major) --
#define BM 128
#define BN 128
#define BK 16

__global__ void __launch_bounds__(256, 2)
gemm_kernel(const float* __restrict__ A, const float* __restrict__ B,
            float* __restrict__ C, int M, int N, int Kd)
{
    __shared__ float As[BK][BM];
    __shared__ float Bs[BK][BN];

    const int t  = threadIdx.x;
    const int tx = t & 15, ty = t >> 4;
    const int m0 = blockIdx.y * BM, n0 = blockIdx.x * BN;

    float acc[8][8] = {};

    for (int k0 = 0; k0 < Kd; k0 += BK) {
#pragma unroll
        for (int q = 0; q < 2; q++) {
            int idx = t + q * 256;
            int arow = idx >> 2, kc = (idx & 3) * 4;
            float4 v = *(const float4*)&A[(size_t)(m0 + arow) * Kd + k0 + kc];
            As[kc + 0][arow] = v.x; As[kc + 1][arow] = v.y;
            As[kc + 2][arow] = v.z; As[kc + 3][arow] = v.w;
        }
#pragma unroll
        for (int q = 0; q < 2; q++) {
            int idx = t + q * 256;
            int brow = idx >> 5, bc = (idx & 31) * 4;
            *(float4*)&Bs[brow][bc] = *(const float4*)&B[(size_t)(k0 + brow) * N + n0 + bc];
        }
        __syncthreads();
#pragma unroll
        for (int kk = 0; kk < BK; kk++) {
            float4 a0 = *(const float4*)&As[kk][ty * 4];
            float4 a1 = *(const float4*)&As[kk][ty * 4 + 64];
            float4 b0 = *(const float4*)&Bs[kk][tx * 4];
            float4 b1 = *(const float4*)&Bs[kk][tx * 4 + 64];
            float av[8] = {a0.x, a0.y, a0.z, a0.w, a1.x, a1.y, a1.z, a1.w};
            float bv[8] = {b0.x, b0.y, b0.z, b0.w, b1.x, b1.y, b1.z, b1.w};
#pragma unroll
            for (int i = 0; i < 8; i++)
#pragma unroll
                for (int j = 0; j < 8; j++)
                    acc[i][j] += av[i] * bv[j];
        }
        __syncthreads();
    }

#pragma unroll
    for (int i = 0; i < 8; i++) {
        int row = m0 + ((i < 4) ? (ty * 4 + i) : (64 + ty * 4 + (i - 4)));
        float4 c0 = make_float4(acc[i][0], acc[i][1], acc[i][2], acc[i][3]);
        float4 c1 = make_float4(acc[i][4], acc[i][5], acc[i][6], acc[i][7]);
        *(float4*)&C[(size_t)row * N + n0 + tx * 4]      = c0;
        *(float4*)&C[(size_t)row * N + n0 + 64 + tx * 4] = c1;
    }
}

// ---------------- launch ------------------------------------------------------
extern "C" void kernel_launch(void* const* d_in, const int* in_sizes, int n_in,
                              void* d_out, int out_size)
{
    (void)in_sizes; (void)n_in; (void)out_size;
    const float* x   = (const float*)d_in[0];
    const float* A0  = (const float*)d_in[1];
    const float* B0  = (const float*)d_in[2];
    const float* C0  = (const float*)d_in[3];
    const float* K0  = (const float*)d_in[4];
    const float* ab0 = (const float*)d_in[5];
    const float* g0  = (const float*)d_in[6];
    const float* bt0 = (const float*)d_in[7];
    const float* A1  = (const float*)d_in[8];
    const float* B1  = (const float*)d_in[9];
    const float* C1  = (const float*)d_in[10];
    const float* K1  = (const float*)d_in[11];
    const float* ab1 = (const float*)d_in[12];
    const float* g1  = (const float*)d_in[13];
    const float* bt1 = (const float*)d_in[14];
    float* out = (float*)d_out;

    float *U, *H, *W01;
    cudaGetSymbolAddress((void**)&U,   g_bufU);
    cudaGetSymbolAddress((void**)&H,   g_bufH);
    cudaGetSymbolAddress((void**)&W01, g_W01);

    cudaFuncSetAttribute(scan_kernel, cudaFuncAttributeMaxDynamicSharedMemorySize,
                         (int)SCAN_SMEM);

    const int M = NB * TT;                        // 32768
    dim3 gBig(S / BN, M / BM);                    // (4, 256)
    dim3 gSmall(S / BN, S / BM);                  // (4, 4)

    // [0] dummy: shifts ncu -s 5 -c 1 onto the 2nd scan kernel
    dummy_kernel<<<1, 32>>>();
    // [1] W01 = C0 @ B1   (fuse: (hs@C0)@B1 = hs@(C0@B1))
    gemm_kernel<<<gSmall, 256>>>(C0, B1, W01, S, S, S);
    // [2] U = x @ B0
    gemm_kernel<<<gBig, 256>>>(x, B0, U, M, S, S);
    // [3] layer 0 scan -> H
    scan_kernel<<<NB * CLU, NTHR, SCAN_SMEM>>>(A0, K0, ab0, g0, bt0, U, H);
    // [4] U = H @ W01
    gemm_kernel<<<gBig, 256>>>(H, W01, U, M, S, S);
    // [5] layer 1 scan -> H   <-- profiled
    scan_kernel<<<NB * CLU, NTHR, SCAN_SMEM>>>(A1, K1, ab1, g1, bt1, U, H);
    // [6] out = H @ C1
    gemm_kernel<<<gBig, 256>>>(H, C1, out, M, S, S);
}